// round 15
// baseline (speedup 1.0000x reference)
#include <cuda_runtime.h>
#include <cuda_fp16.h>
#include <cuda_bf16.h>
#include <cstdint>

#define NNODES 50000
#define NEDGES 500000
#define NGRAPH 64
#define FDIM   128      // H*D
#define NCLS   5
#define SLOPE  0.2f
#define NBLK   ((NNODES + 1023) / 1024)   // 49 scan blocks

// ---------------- scratch (device globals; no allocations allowed) ----------
// Self-restoring protocol: g_count / g_pool / g_cnt are zero at entry of every
// kernel_launch call (CUDA zero-init on first call; consumers rezero them).
__device__ __half g_hh[(size_t)NNODES * FDIM];   // fp16 h for gather path
__device__ float g_x[(size_t)NNODES * FDIM];     // fp32 layer input
__device__ float g_asrc[NNODES * 2];
__device__ float g_adst[NNODES * 2];
__device__ int   g_count[NNODES];
__device__ int   g_rowptr[NNODES + 1];
__device__ int   g_pos[NNODES];
__device__ int   g_bsum[64];
__device__ int   g_srcsorted[NEDGES];
__device__ float g_pool[NGRAPH * FDIM];
__device__ int   g_cnt[NGRAPH];

// int64 detection: odd 32-bit words of small int64 values are all zero.
__device__ __forceinline__ bool is64(const void* p) {
    const int* w = (const int*)p;
    return (w[1] | w[3] | w[5] | w[7]) == 0;
}
__device__ __forceinline__ int load_idx(const void* p, bool i64, long long i) {
    return i64 ? (int)((const long long*)p)[i] : ((const int*)p)[i];
}

// ---------------- CSR build (2 edges per thread, wide loads) -----------------
__global__ void hist_kernel(const void* ei) {
    bool i64 = is64(ei);
    int e = (blockIdx.x * blockDim.x + threadIdx.x) * 2;
    if (e >= NEDGES) return;
    int d0, d1;
    if (i64) {
        longlong2 v = *(const longlong2*)((const long long*)ei + NEDGES + e);
        d0 = (int)v.x; d1 = (int)v.y;
    } else {
        int2 v = *(const int2*)((const int*)ei + NEDGES + e);
        d0 = v.x; d1 = v.y;
    }
    atomicAdd(&g_count[d0], 1);
    atomicAdd(&g_count[d1], 1);
}

// Per-1024-node block scan; also REZEROES g_count for the next call.
__global__ void scanA_kernel() {
    int t = threadIdx.x;
    int base = blockIdx.x * 1024 + t * 4;
    int c0 = 0, c1 = 0, c2 = 0, c3 = 0;
    if (base + 0 < NNODES) { c0 = g_count[base + 0]; g_count[base + 0] = 0; }
    if (base + 1 < NNODES) { c1 = g_count[base + 1]; g_count[base + 1] = 0; }
    if (base + 2 < NNODES) { c2 = g_count[base + 2]; g_count[base + 2] = 0; }
    if (base + 3 < NNODES) { c3 = g_count[base + 3]; g_count[base + 3] = 0; }
    int s = c0 + c1 + c2 + c3;
    int lane = t & 31, warp = t >> 5;
    int incl = s;
#pragma unroll
    for (int o = 1; o < 32; o <<= 1) {
        int u = __shfl_up_sync(0xffffffffu, incl, o);
        if (lane >= o) incl += u;
    }
    __shared__ int wtot[8];
    if (lane == 31) wtot[warp] = incl;
    __syncthreads();
    if (t == 0) {
        int r = 0;
#pragma unroll
        for (int w = 0; w < 8; w++) { int v = wtot[w]; wtot[w] = r; r += v; }
        g_bsum[blockIdx.x] = r;
    }
    __syncthreads();
    int excl = incl - s + wtot[warp];
    if (base + 0 < NNODES) g_rowptr[base + 0] = excl;
    if (base + 1 < NNODES) g_rowptr[base + 1] = excl + c0;
    if (base + 2 < NNODES) g_rowptr[base + 2] = excl + c0 + c1;
    if (base + 3 < NNODES) g_rowptr[base + 3] = excl + c0 + c1 + c2;
}

// scanC with inlined scanB: each block redundantly reduces the block-sum
// prefix it needs (<=48 values, L2-hot).
__global__ void scanC_kernel() {
    __shared__ int soff[2];
    int t = threadIdx.x;
    int B = blockIdx.x >> 2;           // owning scanA block (1024/256 = 4)
    if (t < 64) {
        int v = (t < B) ? g_bsum[t] : 0;
#pragma unroll
        for (int o = 16; o >= 1; o >>= 1)
            v += __shfl_xor_sync(0xffffffffu, v, o);
        if ((t & 31) == 0) soff[t >> 5] = v;
    }
    __syncthreads();
    int offset = soff[0] + soff[1];
    int i = blockIdx.x * 256 + t;
    if (i < NNODES) {
        int r = g_rowptr[i] + offset;
        g_rowptr[i] = r;
        g_pos[i] = r;
    }
    if (i == 0) g_rowptr[NNODES] = NEDGES;
}

__global__ void scatter_kernel(const void* ei) {
    bool i64 = is64(ei);
    int e = (blockIdx.x * blockDim.x + threadIdx.x) * 2;
    if (e >= NEDGES) return;
    int s0, s1, d0, d1;
    if (i64) {
        longlong2 sv = *(const longlong2*)((const long long*)ei + e);
        longlong2 dv = *(const longlong2*)((const long long*)ei + NEDGES + e);
        s0 = (int)sv.x; s1 = (int)sv.y;
        d0 = (int)dv.x; d1 = (int)dv.y;
    } else {
        int2 sv = *(const int2*)((const int*)ei + e);
        int2 dv = *(const int2*)((const int*)ei + NEDGES + e);
        s0 = sv.x; s1 = sv.y;
        d0 = dv.x; d1 = dv.y;
    }
    int p0 = atomicAdd(&g_pos[d0], 1);
    g_srcsorted[p0] = s0;
    int p1 = atomicAdd(&g_pos[d1], 1);
    g_srcsorted[p1] = s1;
}

// ---------------- bf16 helpers ------------------------------------------------
__device__ __forceinline__ unsigned pack_bf16(float lo, float hi) {
    __nv_bfloat162 t = __floats2bfloat162_rn(lo, hi);   // .x = lo bits
    return *reinterpret_cast<unsigned*>(&t);
}
__device__ __forceinline__ void split2(float v0, float v1,
                                       unsigned& h, unsigned& l) {
    float h0 = __bfloat162float(__float2bfloat16_rn(v0));
    float h1 = __bfloat162float(__float2bfloat16_rn(v1));
    h = pack_bf16(h0, h1);
    l = pack_bf16(v0 - h0, v1 - h1);
}

__device__ __forceinline__ void mma_bf16(float c[4],
                                         unsigned a0, unsigned a1, unsigned a2, unsigned a3,
                                         unsigned b0, unsigned b1) {
    asm("mma.sync.aligned.m16n8k16.row.col.f32.bf16.bf16.f32 "
        "{%0,%1,%2,%3}, {%4,%5,%6,%7}, {%8,%9}, {%0,%1,%2,%3};"
        : "+f"(c[0]), "+f"(c[1]), "+f"(c[2]), "+f"(c[3])
        : "r"(a0), "r"(a1), "r"(a2), "r"(a3), "r"(b0), "r"(b1));
}

// ---------------- GEMM (bf16 m16n8k16, 3-pass split) + fused logits ----------
// Block: 64 nodes x 128 cols, 8 warps. Warp w: m-tile (w&3) x col-half (w>>2).
// acc[8][4] = 32 regs -> 4 blocks/SM (2x occupancy of the old 128-node tile).
// Col-half == head, so each warp reduces logits for exactly one head.
__global__ __launch_bounds__(256, 4) void gemm_kernel(
    const float* __restrict__ Xin, int K, const float* __restrict__ W,
    const float* __restrict__ Asrc, const float* __restrict__ Adst)
{
    __shared__ unsigned xsh[64][13];    // stride 13: conflict-free frag loads
    __shared__ unsigned xsl[64][13];
    __shared__ unsigned wh[8][136];
    __shared__ unsigned wl[8][136];
    const float* X = Xin ? Xin : g_x;
    int tid = threadIdx.x, lane = tid & 31, warp = tid >> 5;
    int n0 = blockIdx.x * 64;
    int mt = warp & 3;        // m-tile (16 nodes)
    int ch = warp >> 2;       // col-half (64 cols) == head
    int g = lane >> 2, q = lane & 3;

    float acc[8][4];
#pragma unroll
    for (int j = 0; j < 8; j++) { acc[j][0] = acc[j][1] = acc[j][2] = acc[j][3] = 0.f; }

    for (int k0 = 0; k0 < K; k0 += 16) {
        // ---- stage X tile [64 x 16] as packed bf16 pairs ---------------------
        {
            int r = tid >> 2, qd = tid & 3;       // row, k-quarter (4 floats)
            int n = n0 + r;
            int kb = k0 + qd * 4;
            float v[4] = {0.f, 0.f, 0.f, 0.f};
            if (n < NNODES) {
                if (kb + 3 < K) {
                    float4 u = *(const float4*)&X[(size_t)n * K + kb];
                    v[0] = u.x; v[1] = u.y; v[2] = u.z; v[3] = u.w;
                } else {
#pragma unroll
                    for (int u = 0; u < 4; u++)
                        if (kb + u < K) v[u] = X[(size_t)n * K + kb + u];
                }
            }
            int p0 = qd * 2;
#pragma unroll
            for (int u = 0; u < 2; u++) {
                unsigned ph, pl;
                split2(v[2 * u], v[2 * u + 1], ph, pl);
                xsh[r][p0 + u] = ph;
                xsl[r][p0 + u] = pl;
            }
        }
        // ---- stage W tile [16 x 128] as packed bf16 pairs --------------------
        {
            int pr = tid >> 5, wc = (tid & 31) * 4;
            int kr0 = k0 + 2 * pr, kr1 = kr0 + 1;
            float4 w0 = make_float4(0.f, 0.f, 0.f, 0.f);
            float4 w1 = make_float4(0.f, 0.f, 0.f, 0.f);
            if (kr0 < K) w0 = *(const float4*)&W[(size_t)kr0 * FDIM + wc];
            if (kr1 < K) w1 = *(const float4*)&W[(size_t)kr1 * FDIM + wc];
#pragma unroll
            for (int u = 0; u < 4; u++) {
                float e0 = ((float*)&w0)[u], e1 = ((float*)&w1)[u];
                unsigned ph, pl;
                split2(e0, e1, ph, pl);
                wh[pr][wc + u] = ph;
                wl[pr][wc + u] = pl;
            }
        }
        __syncthreads();

        // ---- A fragments (m16k16 row-major) ---------------------------------
        int ra = mt * 16 + g;
        unsigned ah0 = xsh[ra][q],     ah1 = xsh[ra + 8][q];
        unsigned ah2 = xsh[ra][q + 4], ah3 = xsh[ra + 8][q + 4];
        unsigned al0 = xsl[ra][q],     al1 = xsl[ra + 8][q];
        unsigned al2 = xsl[ra][q + 4], al3 = xsl[ra + 8][q + 4];

#pragma unroll
        for (int j = 0; j < 8; j++) {
            int col = ch * 64 + j * 8 + g;
            unsigned bh0 = wh[q][col];
            unsigned bh1 = wh[q + 4][col];
            unsigned bl0 = wl[q][col];
            unsigned bl1 = wl[q + 4][col];
            mma_bf16(acc[j], ah0, ah1, ah2, ah3, bh0, bh1);
            mma_bf16(acc[j], al0, al1, al2, al3, bh0, bh1);
            mma_bf16(acc[j], ah0, ah1, ah2, ah3, bl0, bl1);
        }
        __syncthreads();
    }

    // ---- epilogue: store h (fp16) + fused fp32 logits (one head per warp) ----
    int nr0 = n0 + mt * 16 + g;
    int nr1 = nr0 + 8;
    float vs0 = 0.f, vd0 = 0.f, vs1 = 0.f, vd1 = 0.f;
#pragma unroll
    for (int j = 0; j < 8; j++) {
        int jc = ch * 64 + j * 8 + 2 * q;
        float as0 = Asrc[jc], as1 = Asrc[jc + 1];
        float ad0 = Adst[jc], ad1 = Adst[jc + 1];
        if (nr0 < NNODES)
            *(__half2*)&g_hh[(size_t)nr0 * FDIM + jc] = __floats2half2_rn(acc[j][0], acc[j][1]);
        if (nr1 < NNODES)
            *(__half2*)&g_hh[(size_t)nr1 * FDIM + jc] = __floats2half2_rn(acc[j][2], acc[j][3]);
        vs0 += acc[j][0] * as0 + acc[j][1] * as1;
        vd0 += acc[j][0] * ad0 + acc[j][1] * ad1;
        vs1 += acc[j][2] * as0 + acc[j][3] * as1;
        vd1 += acc[j][2] * ad0 + acc[j][3] * ad1;
    }
#pragma unroll
    for (int o = 1; o < 4; o <<= 1) {
        vs0 += __shfl_xor_sync(0xffffffffu, vs0, o);
        vd0 += __shfl_xor_sync(0xffffffffu, vd0, o);
        vs1 += __shfl_xor_sync(0xffffffffu, vs1, o);
        vd1 += __shfl_xor_sync(0xffffffffu, vd1, o);
    }
    if (q == 0) {
        if (nr0 < NNODES) {
            g_asrc[nr0 * 2 + ch] = vs0;
            g_adst[nr0 * 2 + ch] = vd0;
        }
        if (nr1 < NNODES) {
            g_asrc[nr1 * 2 + ch] = vs1;
            g_adst[nr1 * 2 + ch] = vd1;
        }
    }
}

// ---------------- aggregation: lane-parallel softmax ---------------------------
// One warp per dst node. Fast path (degree <= 32, the overwhelming case):
// logits/exps stay in registers from the stats pass -- no second gather.
__global__ void agg_kernel(const float* __restrict__ B,
                           const void* batch, const void* ei, int dopool) {
    __shared__ float sm[8][128];
    __shared__ int sb[8];
    int tid = threadIdx.x;
    int n = (blockIdx.x * blockDim.x + tid) >> 5;
    int lane = tid & 31, warp = tid >> 5;
    if (n >= NNODES) return;
    int beg = g_rowptr[n], end = g_rowptr[n + 1];
    float2 adn = *(const float2*)&g_adst[n * 2];
    int f = lane * 4;
    float4 acc = make_float4(0.f, 0.f, 0.f, 0.f);
    int deg = end - beg;

    if (deg <= 32) {
        // ---- fast path: single chunk, everything in registers ----------------
        int i = beg + lane;
        bool v = i < end;
        int src = 0;
        float e0 = -3.0e38f, e1 = -3.0e38f;
        if (v) {
            src = __ldg(&g_srcsorted[i]);
            float2 as = *(const float2*)&g_asrc[src * 2];
            e0 = as.x + adn.x; e0 = (e0 > 0.f) ? e0 : SLOPE * e0;
            e1 = as.y + adn.y; e1 = (e1 > 0.f) ? e1 : SLOPE * e1;
        }
        float c0 = e0, c1 = e1;
#pragma unroll
        for (int o = 16; o >= 1; o >>= 1) {
            c0 = fmaxf(c0, __shfl_xor_sync(0xffffffffu, c0, o));
            c1 = fmaxf(c1, __shfl_xor_sync(0xffffffffu, c1, o));
        }
        float p0 = v ? __expf(e0 - c0) : 0.f;
        float p1 = v ? __expf(e1 - c1) : 0.f;
        float q0 = p0, q1 = p1;
#pragma unroll
        for (int o = 16; o >= 1; o >>= 1) {
            q0 += __shfl_xor_sync(0xffffffffu, q0, o);
            q1 += __shfl_xor_sync(0xffffffffu, q1, o);
        }
        float a0 = p0 / (q0 + 1e-16f);
        float a1 = p1 / (q1 + 1e-16f);
#pragma unroll 4
        for (int j = 0; j < deg; j++) {
            int   sj = __shfl_sync(0xffffffffu, src, j);
            float pa = __shfl_sync(0xffffffffu, a0, j);
            float pb = __shfl_sync(0xffffffffu, a1, j);
            float p  = (lane < 16) ? pa : pb;
            uint2 hv = *(const uint2*)&g_hh[(size_t)sj * FDIM + f];
            float2 fA = __half22float2(*(__half2*)&hv.x);
            float2 fB = __half22float2(*(__half2*)&hv.y);
            acc.x = fmaf(p, fA.x, acc.x);
            acc.y = fmaf(p, fA.y, acc.y);
            acc.z = fmaf(p, fB.x, acc.z);
            acc.w = fmaf(p, fB.y, acc.w);
        }
    } else {
        // ---- general path: two-pass over chunks ------------------------------
        float m0 = -3.0e38f, m1 = -3.0e38f, s0 = 0.f, s1 = 0.f;
        for (int c = beg; c < end; c += 32) {
            int i = c + lane;
            float e0 = -3.0e38f, e1 = -3.0e38f;
            if (i < end) {
                int src = __ldg(&g_srcsorted[i]);
                float2 as = *(const float2*)&g_asrc[src * 2];
                e0 = as.x + adn.x; e0 = (e0 > 0.f) ? e0 : SLOPE * e0;
                e1 = as.y + adn.y; e1 = (e1 > 0.f) ? e1 : SLOPE * e1;
            }
            float c0 = e0, c1 = e1;
#pragma unroll
            for (int o = 16; o >= 1; o >>= 1) {
                c0 = fmaxf(c0, __shfl_xor_sync(0xffffffffu, c0, o));
                c1 = fmaxf(c1, __shfl_xor_sync(0xffffffffu, c1, o));
            }
            float p0 = (i < end) ? __expf(e0 - c0) : 0.f;
            float p1 = (i < end) ? __expf(e1 - c1) : 0.f;
#pragma unroll
            for (int o = 16; o >= 1; o >>= 1) {
                p0 += __shfl_xor_sync(0xffffffffu, p0, o);
                p1 += __shfl_xor_sync(0xffffffffu, p1, o);
            }
            float nm0 = fmaxf(m0, c0), nm1 = fmaxf(m1, c1);
            s0 = s0 * __expf(m0 - nm0) + p0 * __expf(c0 - nm0);
            s1 = s1 * __expf(m1 - nm1) + p1 * __expf(c1 - nm1);
            m0 = nm0; m1 = nm1;
        }
        float inv0 = 1.f / (s0 + 1e-16f);
        float inv1 = 1.f / (s1 + 1e-16f);

        for (int c = beg; c < end; c += 32) {
            int i = c + lane;
            int src = 0; float a0 = 0.f, a1 = 0.f;
            if (i < end) {
                src = __ldg(&g_srcsorted[i]);
                float2 as = *(const float2*)&g_asrc[src * 2];
                float e0 = as.x + adn.x; e0 = (e0 > 0.f) ? e0 : SLOPE * e0;
                float e1 = as.y + adn.y; e1 = (e1 > 0.f) ? e1 : SLOPE * e1;
                a0 = __expf(e0 - m0) * inv0;
                a1 = __expf(e1 - m1) * inv1;
            }
            int cnt = min(32, end - c);
#pragma unroll 4
            for (int j = 0; j < cnt; j++) {
                int   sj = __shfl_sync(0xffffffffu, src, j);
                float pa = __shfl_sync(0xffffffffu, a0, j);
                float pb = __shfl_sync(0xffffffffu, a1, j);
                float p  = (lane < 16) ? pa : pb;
                uint2 hv = *(const uint2*)&g_hh[(size_t)sj * FDIM + f];
                float2 fA = __half22float2(*(__half2*)&hv.x);
                float2 fB = __half22float2(*(__half2*)&hv.y);
                acc.x = fmaf(p, fA.x, acc.x);
                acc.y = fmaf(p, fA.y, acc.y);
                acc.z = fmaf(p, fB.x, acc.z);
                acc.w = fmaf(p, fB.y, acc.w);
            }
        }
    }

    float4 o;
    o.x = fmaxf(acc.x + B[f + 0], 0.f);
    o.y = fmaxf(acc.y + B[f + 1], 0.f);
    o.z = fmaxf(acc.z + B[f + 2], 0.f);
    o.w = fmaxf(acc.w + B[f + 3], 0.f);

    if (!dopool) {
        *(float4*)&g_x[(size_t)n * FDIM + f] = o;
    } else {
        bool i64 = is64(ei);
        int b = load_idx(batch, i64, n);
        if (lane == 0) sb[warp] = b;
        *(float4*)&sm[warp][f] = o;
        __syncthreads();
        bool uni = true;
#pragma unroll
        for (int w = 1; w < 8; w++) uni &= (sb[w] == sb[0]);
        if (uni) {
            if (tid < 128) {
                float sum = 0.f;
#pragma unroll
                for (int w = 0; w < 8; w++) sum += sm[w][tid];
                atomicAdd(&g_pool[sb[0] * FDIM + tid], sum);
            }
            if (tid == 0) atomicAdd(&g_cnt[sb[0]], 8);
        } else {
            atomicAdd(&g_pool[b * FDIM + f + 0], o.x);
            atomicAdd(&g_pool[b * FDIM + f + 1], o.y);
            atomicAdd(&g_pool[b * FDIM + f + 2], o.z);
            atomicAdd(&g_pool[b * FDIM + f + 3], o.w);
            if (lane == 0) atomicAdd(&g_cnt[b], 1);
        }
    }
}

// ---------------- final linear + sigmoid (+ pool cleanup for next call) -------
__global__ void final_kernel(const float* __restrict__ LW,
                             const float* __restrict__ LB,
                             float* __restrict__ out) {
    int t = threadIdx.x;
    if (t < NGRAPH * NCLS) {
        int g = t / NCLS, c = t % NCLS;
        float cnt = (float)g_cnt[g];
        if (cnt < 1.f) cnt = 1.f;
        float sum = 0.f;
        for (int k = 0; k < FDIM; k++)
            sum = fmaf(g_pool[g * FDIM + k], LW[k * NCLS + c], sum);
        float z = sum / cnt + LB[c];
        out[t] = 1.f / (1.f + expf(-z));
    }
    __syncthreads();
    for (int k = t; k < NGRAPH * FDIM; k += blockDim.x) g_pool[k] = 0.f;
    if (t < NGRAPH) g_cnt[t] = 0;
}

// ---------------- launch ------------------------------------------------------
// Single-stream. gemm0 (independent of CSR) is in launch slot 4 so ncu's
// fixed-position capture profiles it (verifies the occupancy prediction).
extern "C" void kernel_launch(void* const* d_in, const int* in_sizes, int n_in,
                              void* d_out, int out_size) {
    const float* x = (const float*)d_in[0];
    const void* ei = d_in[1];
    const void* batch = d_in[2];
    const float* W[4]  = {(const float*)d_in[3],  (const float*)d_in[7],
                          (const float*)d_in[11], (const float*)d_in[15]};
    const float* As[4] = {(const float*)d_in[4],  (const float*)d_in[8],
                          (const float*)d_in[12], (const float*)d_in[16]};
    const float* Ad[4] = {(const float*)d_in[5],  (const float*)d_in[9],
                          (const float*)d_in[13], (const float*)d_in[17]};
    const float* Bb[4] = {(const float*)d_in[6],  (const float*)d_in[10],
                          (const float*)d_in[14], (const float*)d_in[18]};
    const float* LW = (const float*)d_in[19];
    const float* LB = (const float*)d_in[20];
    float* out = (float*)d_out;

    int gemm_blocks = (NNODES + 63) / 64;
    int warp_blocks = (NNODES * 32 + 255) / 256;
    int edge2_blocks = (NEDGES / 2 + 255) / 256;

    hist_kernel<<<edge2_blocks, 256>>>(ei);
    scanA_kernel<<<NBLK, 256>>>();
    scanC_kernel<<<(NNODES + 255) / 256, 256>>>();
    gemm_kernel<<<gemm_blocks, 256>>>(x, 4, W[0], As[0], Ad[0]);   // slot 4: profiled
    scatter_kernel<<<edge2_blocks, 256>>>(ei);

    for (int l = 0; l < 4; l++) {
        if (l > 0)
            gemm_kernel<<<gemm_blocks, 256>>>(nullptr, FDIM, W[l], As[l], Ad[l]);
        agg_kernel<<<warp_blocks, 256>>>(Bb[l], batch, ei, (l == 3) ? 1 : 0);
    }
    final_kernel<<<1, 512>>>(LW, LB, out);
}

// round 16
// speedup vs baseline: 1.0347x; 1.0347x over previous
#include <cuda_runtime.h>
#include <cuda_fp16.h>
#include <cuda_bf16.h>
#include <cstdint>

#define NNODES 50000
#define NEDGES 500000
#define NGRAPH 64
#define FDIM   128      // H*D
#define NCLS   5
#define SLOPE  0.2f
#define NBLK   ((NNODES + 1023) / 1024)   // 49 scan blocks

// ---------------- scratch (device globals; no allocations allowed) ----------
// Self-restoring protocol: g_count / g_pool / g_cnt are zero at entry of every
// kernel_launch call (CUDA zero-init on first call; consumers rezero them).
__device__ __half g_hh[(size_t)NNODES * FDIM];   // fp16 h for gather path
__device__ float g_x[(size_t)NNODES * FDIM];     // fp32 layer input
__device__ float g_asrc[NNODES * 2];
__device__ float g_adst[NNODES * 2];
__device__ int   g_count[NNODES];
__device__ int   g_rowptr[NNODES + 1];
__device__ int   g_pos[NNODES];
__device__ int   g_bsum[64];
__device__ int   g_srcsorted[NEDGES];
__device__ float g_pool[NGRAPH * FDIM];
__device__ int   g_cnt[NGRAPH];

// int64 detection: odd 32-bit words of small int64 values are all zero.
__device__ __forceinline__ bool is64(const void* p) {
    const int* w = (const int*)p;
    return (w[1] | w[3] | w[5] | w[7]) == 0;
}
__device__ __forceinline__ int load_idx(const void* p, bool i64, long long i) {
    return i64 ? (int)((const long long*)p)[i] : ((const int*)p)[i];
}

// ---------------- CSR build (2 edges per thread, wide loads) -----------------
__global__ void hist_kernel(const void* ei) {
    bool i64 = is64(ei);
    int e = (blockIdx.x * blockDim.x + threadIdx.x) * 2;
    if (e >= NEDGES) return;
    int d0, d1;
    if (i64) {
        longlong2 v = *(const longlong2*)((const long long*)ei + NEDGES + e);
        d0 = (int)v.x; d1 = (int)v.y;
    } else {
        int2 v = *(const int2*)((const int*)ei + NEDGES + e);
        d0 = v.x; d1 = v.y;
    }
    atomicAdd(&g_count[d0], 1);
    atomicAdd(&g_count[d1], 1);
}

// Per-1024-node block scan; also REZEROES g_count for the next call.
__global__ void scanA_kernel() {
    int t = threadIdx.x;
    int base = blockIdx.x * 1024 + t * 4;
    int c0 = 0, c1 = 0, c2 = 0, c3 = 0;
    if (base + 0 < NNODES) { c0 = g_count[base + 0]; g_count[base + 0] = 0; }
    if (base + 1 < NNODES) { c1 = g_count[base + 1]; g_count[base + 1] = 0; }
    if (base + 2 < NNODES) { c2 = g_count[base + 2]; g_count[base + 2] = 0; }
    if (base + 3 < NNODES) { c3 = g_count[base + 3]; g_count[base + 3] = 0; }
    int s = c0 + c1 + c2 + c3;
    int lane = t & 31, warp = t >> 5;
    int incl = s;
#pragma unroll
    for (int o = 1; o < 32; o <<= 1) {
        int u = __shfl_up_sync(0xffffffffu, incl, o);
        if (lane >= o) incl += u;
    }
    __shared__ int wtot[8];
    if (lane == 31) wtot[warp] = incl;
    __syncthreads();
    if (t == 0) {
        int r = 0;
#pragma unroll
        for (int w = 0; w < 8; w++) { int v = wtot[w]; wtot[w] = r; r += v; }
        g_bsum[blockIdx.x] = r;
    }
    __syncthreads();
    int excl = incl - s + wtot[warp];
    if (base + 0 < NNODES) g_rowptr[base + 0] = excl;
    if (base + 1 < NNODES) g_rowptr[base + 1] = excl + c0;
    if (base + 2 < NNODES) g_rowptr[base + 2] = excl + c0 + c1;
    if (base + 3 < NNODES) g_rowptr[base + 3] = excl + c0 + c1 + c2;
}

// scanC with inlined scanB: each block redundantly reduces the block-sum
// prefix it needs (<=48 values, L2-hot).
__global__ void scanC_kernel() {
    __shared__ int soff[2];
    int t = threadIdx.x;
    int B = blockIdx.x >> 2;           // owning scanA block (1024/256 = 4)
    if (t < 64) {
        int v = (t < B) ? g_bsum[t] : 0;
#pragma unroll
        for (int o = 16; o >= 1; o >>= 1)
            v += __shfl_xor_sync(0xffffffffu, v, o);
        if ((t & 31) == 0) soff[t >> 5] = v;
    }
    __syncthreads();
    int offset = soff[0] + soff[1];
    int i = blockIdx.x * 256 + t;
    if (i < NNODES) {
        int r = g_rowptr[i] + offset;
        g_rowptr[i] = r;
        g_pos[i] = r;
    }
    if (i == 0) g_rowptr[NNODES] = NEDGES;
}

__global__ void scatter_kernel(const void* ei) {
    bool i64 = is64(ei);
    int e = (blockIdx.x * blockDim.x + threadIdx.x) * 2;
    if (e >= NEDGES) return;
    int s0, s1, d0, d1;
    if (i64) {
        longlong2 sv = *(const longlong2*)((const long long*)ei + e);
        longlong2 dv = *(const longlong2*)((const long long*)ei + NEDGES + e);
        s0 = (int)sv.x; s1 = (int)sv.y;
        d0 = (int)dv.x; d1 = (int)dv.y;
    } else {
        int2 sv = *(const int2*)((const int*)ei + e);
        int2 dv = *(const int2*)((const int*)ei + NEDGES + e);
        s0 = sv.x; s1 = sv.y;
        d0 = dv.x; d1 = dv.y;
    }
    int p0 = atomicAdd(&g_pos[d0], 1);
    g_srcsorted[p0] = s0;
    int p1 = atomicAdd(&g_pos[d1], 1);
    g_srcsorted[p1] = s1;
}

// ---------------- bf16 helpers ------------------------------------------------
__device__ __forceinline__ unsigned pack_bf16(float lo, float hi) {
    __nv_bfloat162 t = __floats2bfloat162_rn(lo, hi);   // .x = lo bits
    return *reinterpret_cast<unsigned*>(&t);
}
__device__ __forceinline__ void split2(float v0, float v1,
                                       unsigned& h, unsigned& l) {
    float h0 = __bfloat162float(__float2bfloat16_rn(v0));
    float h1 = __bfloat162float(__float2bfloat16_rn(v1));
    h = pack_bf16(h0, h1);
    l = pack_bf16(v0 - h0, v1 - h1);
}

__device__ __forceinline__ void mma_bf16(float c[4],
                                         unsigned a0, unsigned a1, unsigned a2, unsigned a3,
                                         unsigned b0, unsigned b1) {
    asm("mma.sync.aligned.m16n8k16.row.col.f32.bf16.bf16.f32 "
        "{%0,%1,%2,%3}, {%4,%5,%6,%7}, {%8,%9}, {%0,%1,%2,%3};"
        : "+f"(c[0]), "+f"(c[1]), "+f"(c[2]), "+f"(c[3])
        : "r"(a0), "r"(a1), "r"(a2), "r"(a3), "r"(b0), "r"(b1));
}

// ---------------- GEMM (bf16 m16n8k16, 3-pass split) + fused logits ----------
// Block: 64 nodes x 128 cols, 8 warps. Warp w: m-tile (w&3) x col-half (w>>2).
// Epilogue stages fp16 h through smem -> fully coalesced 16B global stores.
__global__ __launch_bounds__(256, 4) void gemm_kernel(
    const float* __restrict__ Xin, int K, const float* __restrict__ W,
    const float* __restrict__ Asrc, const float* __restrict__ Adst)
{
    __shared__ unsigned xsh[64][13];    // stride 13: conflict-free frag loads
    __shared__ unsigned xsl[64][13];
    __shared__ unsigned wh[8][136];
    __shared__ unsigned wl[8][136];
    __shared__ __half  hstage[64][136]; // epilogue staging (272B row stride)
    const float* X = Xin ? Xin : g_x;
    int tid = threadIdx.x, lane = tid & 31, warp = tid >> 5;
    int n0 = blockIdx.x * 64;
    int mt = warp & 3;        // m-tile (16 nodes)
    int ch = warp >> 2;       // col-half (64 cols) == head
    int g = lane >> 2, q = lane & 3;

    float acc[8][4];
#pragma unroll
    for (int j = 0; j < 8; j++) { acc[j][0] = acc[j][1] = acc[j][2] = acc[j][3] = 0.f; }

    for (int k0 = 0; k0 < K; k0 += 16) {
        // ---- stage X tile [64 x 16] as packed bf16 pairs ---------------------
        {
            int r = tid >> 2, qd = tid & 3;       // row, k-quarter (4 floats)
            int n = n0 + r;
            int kb = k0 + qd * 4;
            float v[4] = {0.f, 0.f, 0.f, 0.f};
            if (n < NNODES) {
                if (kb + 3 < K) {
                    float4 u = *(const float4*)&X[(size_t)n * K + kb];
                    v[0] = u.x; v[1] = u.y; v[2] = u.z; v[3] = u.w;
                } else {
#pragma unroll
                    for (int u = 0; u < 4; u++)
                        if (kb + u < K) v[u] = X[(size_t)n * K + kb + u];
                }
            }
            int p0 = qd * 2;
#pragma unroll
            for (int u = 0; u < 2; u++) {
                unsigned ph, pl;
                split2(v[2 * u], v[2 * u + 1], ph, pl);
                xsh[r][p0 + u] = ph;
                xsl[r][p0 + u] = pl;
            }
        }
        // ---- stage W tile [16 x 128] as packed bf16 pairs --------------------
        {
            int pr = tid >> 5, wc = (tid & 31) * 4;
            int kr0 = k0 + 2 * pr, kr1 = kr0 + 1;
            float4 w0 = make_float4(0.f, 0.f, 0.f, 0.f);
            float4 w1 = make_float4(0.f, 0.f, 0.f, 0.f);
            if (kr0 < K) w0 = *(const float4*)&W[(size_t)kr0 * FDIM + wc];
            if (kr1 < K) w1 = *(const float4*)&W[(size_t)kr1 * FDIM + wc];
#pragma unroll
            for (int u = 0; u < 4; u++) {
                float e0 = ((float*)&w0)[u], e1 = ((float*)&w1)[u];
                unsigned ph, pl;
                split2(e0, e1, ph, pl);
                wh[pr][wc + u] = ph;
                wl[pr][wc + u] = pl;
            }
        }
        __syncthreads();

        // ---- A fragments (m16k16 row-major) ---------------------------------
        int ra = mt * 16 + g;
        unsigned ah0 = xsh[ra][q],     ah1 = xsh[ra + 8][q];
        unsigned ah2 = xsh[ra][q + 4], ah3 = xsh[ra + 8][q + 4];
        unsigned al0 = xsl[ra][q],     al1 = xsl[ra + 8][q];
        unsigned al2 = xsl[ra][q + 4], al3 = xsl[ra + 8][q + 4];

#pragma unroll
        for (int j = 0; j < 8; j++) {
            int col = ch * 64 + j * 8 + g;
            unsigned bh0 = wh[q][col];
            unsigned bh1 = wh[q + 4][col];
            unsigned bl0 = wl[q][col];
            unsigned bl1 = wl[q + 4][col];
            mma_bf16(acc[j], ah0, ah1, ah2, ah3, bh0, bh1);
            mma_bf16(acc[j], al0, al1, al2, al3, bh0, bh1);
            mma_bf16(acc[j], ah0, ah1, ah2, ah3, bl0, bl1);
        }
        __syncthreads();
    }

    // ---- epilogue: stage fp16 h in smem + fused fp32 logits ------------------
    int r0 = mt * 16 + g;         // local rows
    int r1 = r0 + 8;
    float vs0 = 0.f, vd0 = 0.f, vs1 = 0.f, vd1 = 0.f;
#pragma unroll
    for (int j = 0; j < 8; j++) {
        int jc = ch * 64 + j * 8 + 2 * q;
        float as0 = Asrc[jc], as1 = Asrc[jc + 1];
        float ad0 = Adst[jc], ad1 = Adst[jc + 1];
        *(__half2*)&hstage[r0][jc] = __floats2half2_rn(acc[j][0], acc[j][1]);
        *(__half2*)&hstage[r1][jc] = __floats2half2_rn(acc[j][2], acc[j][3]);
        vs0 += acc[j][0] * as0 + acc[j][1] * as1;
        vd0 += acc[j][0] * ad0 + acc[j][1] * ad1;
        vs1 += acc[j][2] * as0 + acc[j][3] * as1;
        vd1 += acc[j][2] * ad0 + acc[j][3] * ad1;
    }
#pragma unroll
    for (int o = 1; o < 4; o <<= 1) {
        vs0 += __shfl_xor_sync(0xffffffffu, vs0, o);
        vd0 += __shfl_xor_sync(0xffffffffu, vd0, o);
        vs1 += __shfl_xor_sync(0xffffffffu, vs1, o);
        vd1 += __shfl_xor_sync(0xffffffffu, vd1, o);
    }
    if (q == 0) {
        int nr0 = n0 + r0, nr1 = n0 + r1;
        if (nr0 < NNODES) {
            g_asrc[nr0 * 2 + ch] = vs0;
            g_adst[nr0 * 2 + ch] = vd0;
        }
        if (nr1 < NNODES) {
            g_asrc[nr1 * 2 + ch] = vs1;
            g_adst[nr1 * 2 + ch] = vd1;
        }
    }
    __syncthreads();
    // coalesced copy-out: 64 rows x 128 halfs = 1024 x 16B chunks
#pragma unroll
    for (int c = tid; c < 1024; c += 256) {
        int r = c >> 4, o = (c & 15) * 8;
        int n = n0 + r;
        if (n < NNODES) {
            uint4 v = *(const uint4*)&hstage[r][o];
            *(uint4*)&g_hh[(size_t)n * FDIM + o] = v;
        }
    }
}

// ---------------- aggregation: lane-parallel softmax ---------------------------
// One warp per dst node. Fast path (degree <= 32, the overwhelming case):
// logits/exps stay in registers from the stats pass -- no second gather.
__global__ void agg_kernel(const float* __restrict__ B,
                           const void* batch, const void* ei, int dopool) {
    __shared__ float sm[8][128];
    __shared__ int sb[8];
    int tid = threadIdx.x;
    int n = (blockIdx.x * blockDim.x + tid) >> 5;
    int lane = tid & 31, warp = tid >> 5;
    if (n >= NNODES) return;
    int beg = g_rowptr[n], end = g_rowptr[n + 1];
    float2 adn = *(const float2*)&g_adst[n * 2];
    int f = lane * 4;
    float4 acc = make_float4(0.f, 0.f, 0.f, 0.f);
    int deg = end - beg;

    if (deg <= 32) {
        // ---- fast path: single chunk, everything in registers ----------------
        int i = beg + lane;
        bool v = i < end;
        int src = 0;
        float e0 = -3.0e38f, e1 = -3.0e38f;
        if (v) {
            src = __ldg(&g_srcsorted[i]);
            float2 as = *(const float2*)&g_asrc[src * 2];
            e0 = as.x + adn.x; e0 = (e0 > 0.f) ? e0 : SLOPE * e0;
            e1 = as.y + adn.y; e1 = (e1 > 0.f) ? e1 : SLOPE * e1;
        }
        float c0 = e0, c1 = e1;
#pragma unroll
        for (int o = 16; o >= 1; o >>= 1) {
            c0 = fmaxf(c0, __shfl_xor_sync(0xffffffffu, c0, o));
            c1 = fmaxf(c1, __shfl_xor_sync(0xffffffffu, c1, o));
        }
        float p0 = v ? __expf(e0 - c0) : 0.f;
        float p1 = v ? __expf(e1 - c1) : 0.f;
        float q0 = p0, q1 = p1;
#pragma unroll
        for (int o = 16; o >= 1; o >>= 1) {
            q0 += __shfl_xor_sync(0xffffffffu, q0, o);
            q1 += __shfl_xor_sync(0xffffffffu, q1, o);
        }
        float a0 = p0 / (q0 + 1e-16f);
        float a1 = p1 / (q1 + 1e-16f);
#pragma unroll 4
        for (int j = 0; j < deg; j++) {
            int   sj = __shfl_sync(0xffffffffu, src, j);
            float pa = __shfl_sync(0xffffffffu, a0, j);
            float pb = __shfl_sync(0xffffffffu, a1, j);
            float p  = (lane < 16) ? pa : pb;
            uint2 hv = *(const uint2*)&g_hh[(size_t)sj * FDIM + f];
            float2 fA = __half22float2(*(__half2*)&hv.x);
            float2 fB = __half22float2(*(__half2*)&hv.y);
            acc.x = fmaf(p, fA.x, acc.x);
            acc.y = fmaf(p, fA.y, acc.y);
            acc.z = fmaf(p, fB.x, acc.z);
            acc.w = fmaf(p, fB.y, acc.w);
        }
    } else {
        // ---- general path: two-pass over chunks ------------------------------
        float m0 = -3.0e38f, m1 = -3.0e38f, s0 = 0.f, s1 = 0.f;
        for (int c = beg; c < end; c += 32) {
            int i = c + lane;
            float e0 = -3.0e38f, e1 = -3.0e38f;
            if (i < end) {
                int src = __ldg(&g_srcsorted[i]);
                float2 as = *(const float2*)&g_asrc[src * 2];
                e0 = as.x + adn.x; e0 = (e0 > 0.f) ? e0 : SLOPE * e0;
                e1 = as.y + adn.y; e1 = (e1 > 0.f) ? e1 : SLOPE * e1;
            }
            float c0 = e0, c1 = e1;
#pragma unroll
            for (int o = 16; o >= 1; o >>= 1) {
                c0 = fmaxf(c0, __shfl_xor_sync(0xffffffffu, c0, o));
                c1 = fmaxf(c1, __shfl_xor_sync(0xffffffffu, c1, o));
            }
            float p0 = (i < end) ? __expf(e0 - c0) : 0.f;
            float p1 = (i < end) ? __expf(e1 - c1) : 0.f;
#pragma unroll
            for (int o = 16; o >= 1; o >>= 1) {
                p0 += __shfl_xor_sync(0xffffffffu, p0, o);
                p1 += __shfl_xor_sync(0xffffffffu, p1, o);
            }
            float nm0 = fmaxf(m0, c0), nm1 = fmaxf(m1, c1);
            s0 = s0 * __expf(m0 - nm0) + p0 * __expf(c0 - nm0);
            s1 = s1 * __expf(m1 - nm1) + p1 * __expf(c1 - nm1);
            m0 = nm0; m1 = nm1;
        }
        float inv0 = 1.f / (s0 + 1e-16f);
        float inv1 = 1.f / (s1 + 1e-16f);

        for (int c = beg; c < end; c += 32) {
            int i = c + lane;
            int src = 0; float a0 = 0.f, a1 = 0.f;
            if (i < end) {
                src = __ldg(&g_srcsorted[i]);
                float2 as = *(const float2*)&g_asrc[src * 2];
                float e0 = as.x + adn.x; e0 = (e0 > 0.f) ? e0 : SLOPE * e0;
                float e1 = as.y + adn.y; e1 = (e1 > 0.f) ? e1 : SLOPE * e1;
                a0 = __expf(e0 - m0) * inv0;
                a1 = __expf(e1 - m1) * inv1;
            }
            int cnt = min(32, end - c);
#pragma unroll 4
            for (int j = 0; j < cnt; j++) {
                int   sj = __shfl_sync(0xffffffffu, src, j);
                float pa = __shfl_sync(0xffffffffu, a0, j);
                float pb = __shfl_sync(0xffffffffu, a1, j);
                float p  = (lane < 16) ? pa : pb;
                uint2 hv = *(const uint2*)&g_hh[(size_t)sj * FDIM + f];
                float2 fA = __half22float2(*(__half2*)&hv.x);
                float2 fB = __half22float2(*(__half2*)&hv.y);
                acc.x = fmaf(p, fA.x, acc.x);
                acc.y = fmaf(p, fA.y, acc.y);
                acc.z = fmaf(p, fB.x, acc.z);
                acc.w = fmaf(p, fB.y, acc.w);
            }
        }
    }

    float4 o;
    o.x = fmaxf(acc.x + B[f + 0], 0.f);
    o.y = fmaxf(acc.y + B[f + 1], 0.f);
    o.z = fmaxf(acc.z + B[f + 2], 0.f);
    o.w = fmaxf(acc.w + B[f + 3], 0.f);

    if (!dopool) {
        *(float4*)&g_x[(size_t)n * FDIM + f] = o;
    } else {
        bool i64 = is64(ei);
        int b = load_idx(batch, i64, n);
        if (lane == 0) sb[warp] = b;
        *(float4*)&sm[warp][f] = o;
        __syncthreads();
        bool uni = true;
#pragma unroll
        for (int w = 1; w < 8; w++) uni &= (sb[w] == sb[0]);
        if (uni) {
            if (tid < 128) {
                float sum = 0.f;
#pragma unroll
                for (int w = 0; w < 8; w++) sum += sm[w][tid];
                atomicAdd(&g_pool[sb[0] * FDIM + tid], sum);
            }
            if (tid == 0) atomicAdd(&g_cnt[sb[0]], 8);
        } else {
            atomicAdd(&g_pool[b * FDIM + f + 0], o.x);
            atomicAdd(&g_pool[b * FDIM + f + 1], o.y);
            atomicAdd(&g_pool[b * FDIM + f + 2], o.z);
            atomicAdd(&g_pool[b * FDIM + f + 3], o.w);
            if (lane == 0) atomicAdd(&g_cnt[b], 1);
        }
    }
}

// ---------------- final linear + sigmoid (+ pool cleanup for next call) -------
__global__ void final_kernel(const float* __restrict__ LW,
                             const float* __restrict__ LB,
                             float* __restrict__ out) {
    int t = threadIdx.x;
    if (t < NGRAPH * NCLS) {
        int g = t / NCLS, c = t % NCLS;
        float cnt = (float)g_cnt[g];
        if (cnt < 1.f) cnt = 1.f;
        float sum = 0.f;
        for (int k = 0; k < FDIM; k++)
            sum = fmaf(g_pool[g * FDIM + k], LW[k * NCLS + c], sum);
        float z = sum / cnt + LB[c];
        out[t] = 1.f / (1.f + expf(-z));
    }
    __syncthreads();
    for (int k = t; k < NGRAPH * FDIM; k += blockDim.x) g_pool[k] = 0.f;
    if (t < NGRAPH) g_cnt[t] = 0;
}

// ---------------- launch ------------------------------------------------------
// Single-stream. gemm0 (independent of CSR) is in launch slot 4 so ncu's
// fixed-position capture profiles it (verifies the epilogue-store prediction).
extern "C" void kernel_launch(void* const* d_in, const int* in_sizes, int n_in,
                              void* d_out, int out_size) {
    const float* x = (const float*)d_in[0];
    const void* ei = d_in[1];
    const void* batch = d_in[2];
    const float* W[4]  = {(const float*)d_in[3],  (const float*)d_in[7],
                          (const float*)d_in[11], (const float*)d_in[15]};
    const float* As[4] = {(const float*)d_in[4],  (const float*)d_in[8],
                          (const float*)d_in[12], (const float*)d_in[16]};
    const float* Ad[4] = {(const float*)d_in[5],  (const float*)d_in[9],
                          (const float*)d_in[13], (const float*)d_in[17]};
    const float* Bb[4] = {(const float*)d_in[6],  (const float*)d_in[10],
                          (const float*)d_in[14], (const float*)d_in[18]};
    const float* LW = (const float*)d_in[19];
    const float* LB = (const float*)d_in[20];
    float* out = (float*)d_out;

    int gemm_blocks = (NNODES + 63) / 64;
    int warp_blocks = (NNODES * 32 + 255) / 256;
    int edge2_blocks = (NEDGES / 2 + 255) / 256;

    hist_kernel<<<edge2_blocks, 256>>>(ei);
    scanA_kernel<<<NBLK, 256>>>();
    scanC_kernel<<<(NNODES + 255) / 256, 256>>>();
    gemm_kernel<<<gemm_blocks, 256>>>(x, 4, W[0], As[0], Ad[0]);   // slot 4: profiled
    scatter_kernel<<<edge2_blocks, 256>>>(ei);

    for (int l = 0; l < 4; l++) {
        if (l > 0)
            gemm_kernel<<<gemm_blocks, 256>>>(nullptr, FDIM, W[l], As[l], Ad[l]);
        agg_kernel<<<warp_blocks, 256>>>(Bb[l], batch, ei, (l == 3) ? 1 : 0);
    }
    final_kernel<<<1, 512>>>(LW, LB, out);
}